// round 13
// baseline (speedup 1.0000x reference)
#include <cuda_runtime.h>
#include <math_constants.h>

// Chamfer loss: N=8, V=4096, C=3 — bucket-pruned exact nearest neighbor.
// Brute force is fma-pipe-bound at ~43us (268M pairs). Instead: bin both
// point sets into 128 x-buckets, then each query expands outward from its
// own bucket, pruning exactly when (x-gap)^2 >= best squared distance.
// Expected ~8x fewer pairs. Exact min (d^2 >= dx^2; edge buckets treated
// as unbounded so clamped outliers are never wrongly pruned).
// Scatter order inside a bucket is atomics-nondeterministic, but min is
// order-independent in exact float arithmetic and the final sum runs over
// ORIGINAL point indices -> bit-identical output every launch.

#define NB 8
#define VPTS 4096
#define NBKT 128
#define XMIN (-4.0f)
#define BW (0.0625f)          // bucket width = 8/128
#define INVBW (16.0f)
#define NSETS 16              // 2 sets x 8 batches
#define NQTOT (2 * NB * VPTS) // 65536
#define CTHREADS 128
#define CBLOCKS (NQTOT / CTHREADS)   // 512

__device__ float4   g_pts[NSETS * VPTS];        // binned points; .w = orig idx bits
__device__ int      g_bstart[NSETS * (NBKT + 1)];
__device__ float    g_dist[NQTOT];              // per-query NN distance, orig order
__device__ unsigned g_cnt_final;                // zero-init; reset after use

__device__ __forceinline__ int bucket_of(float v) {
    int b = (int)floorf((v - XMIN) * INVBW);
    return min(NBKT - 1, max(0, b));
}

// ---------------- binning: one block per (set,batch) ----------------
__global__ __launch_bounds__(256)
void bin_kernel(const float* __restrict__ x, const float* __restrict__ y) {
    const int bi = blockIdx.x;            // 0..15: set = bi>>3, batch = bi&7
    const int s  = bi >> 3;
    const int n  = bi & 7;
    const float* __restrict__ P = (s ? y : x) + (size_t)n * VPTS * 3;
    const int tid = threadIdx.x;

    __shared__ int hist[NBKT];
    __shared__ int offs[NBKT];

    if (tid < NBKT) hist[tid] = 0;
    __syncthreads();

    for (int i = tid; i < VPTS; i += 256)
        atomicAdd(&hist[bucket_of(P[3 * i])], 1);
    __syncthreads();

    if (tid == 0) {
        int run = 0;
        for (int k = 0; k < NBKT; k++) {
            g_bstart[bi * (NBKT + 1) + k] = run;
            offs[k] = run;
            run += hist[k];
        }
        g_bstart[bi * (NBKT + 1) + NBKT] = VPTS;
    }
    __syncthreads();

    for (int i = tid; i < VPTS; i += 256) {
        float a = P[3 * i], b = P[3 * i + 1], c = P[3 * i + 2];
        int k = bucket_of(a);
        int pos = atomicAdd(&offs[k], 1);
        g_pts[bi * VPTS + pos] = make_float4(a, b, c, __int_as_float(i));
    }
}

// ---------------- pruned NN + fused final reduction ----------------
__device__ __forceinline__ void scan_bucket(const float4* __restrict__ TP,
                                            int t0, int t1, float4 q,
                                            float& best) {
    #pragma unroll 4
    for (int t = t0; t < t1; t++) {
        float4 p = __ldg(&TP[t]);
        float dx = q.x - p.x;
        float dy = q.y - p.y;
        float dz = q.z - p.z;
        float d2 = fmaf(dx, dx, fmaf(dy, dy, dz * dz));
        best = fminf(best, d2);
    }
}

__global__ __launch_bounds__(CTHREADS)
void chamfer_pruned(float* __restrict__ out) {
    const int tid = threadIdx.x;
    const int qid = blockIdx.x * CTHREADS + tid;   // 0..65535
    const int s   = qid / (NB * VPTS);             // query set
    const int rem = qid - s * (NB * VPTS);
    const int n   = rem / VPTS;
    const int i   = rem - n * VPTS;                // position in binned order

    const float4 q = g_pts[(s * NB + n) * VPTS + i];
    const int tb = (1 - s) * NB + n;               // target (set,batch)
    const float4* __restrict__ TP = g_pts + tb * VPTS;
    const int*    __restrict__ bs = g_bstart + tb * (NBKT + 1);

    const int k0 = bucket_of(q.x);
    float best = CUDART_INF_F;

    // own bucket first
    scan_bucket(TP, bs[k0], bs[k0 + 1], q, best);

    // expand rings; prune exactly on x-gap^2 >= best d^2
    int dl = k0 - 1, dr = k0 + 1;
    for (;;) {
        bool doneL, doneR;
        float gl = 0.f, gr = 0.f;
        if (dl < 0) doneL = true;
        else { gl = q.x - (XMIN + (float)(dl + 1) * BW); doneL = (gl * gl >= best); }
        if (dr > NBKT - 1) doneR = true;
        else { gr = (XMIN + (float)dr * BW) - q.x; doneR = (gr * gr >= best); }
        if (doneL && doneR) break;
        if (!doneL) { scan_bucket(TP, bs[dl], bs[dl + 1], q, best); dl--; }
        if (!doneR) { scan_bucket(TP, bs[dr], bs[dr + 1], q, best); dr++; }
    }

    // write to ORIGINAL index order (deterministic final sum)
    const int orig = __float_as_int(q.w);
    g_dist[(s * NB + n) * VPTS + orig] = sqrtf(fmaxf(best, 0.0f));
    __threadfence();
    __syncthreads();

    // elect last block for the final deterministic reduction
    __shared__ bool isLast;
    if (tid == 0)
        isLast = (atomicAdd(&g_cnt_final, 1u) == CBLOCKS - 1);
    __syncthreads();

    if (isLast) {
        __threadfence();   // acquire all g_dist writes
        // 65536 floats, 128 threads: 512 consecutive each, fixed order.
        const float4* dv = reinterpret_cast<const float4*>(g_dist) + tid * 128;
        float a0 = 0.f, a1 = 0.f, a2 = 0.f, a3 = 0.f;
        #pragma unroll 4
        for (int j = 0; j < 128; j++) {
            float4 v = dv[j];
            a0 += v.x; a1 += v.y; a2 += v.z; a3 += v.w;
        }
        float v = (a0 + a1) + (a2 + a3);
        #pragma unroll
        for (int off = 16; off > 0; off >>= 1)
            v += __shfl_down_sync(0xffffffffu, v, off);
        __shared__ float ws[CTHREADS / 32];
        if ((tid & 31) == 0) ws[tid >> 5] = v;
        __syncthreads();
        if (tid == 0) {
            float t = 0.f;
            #pragma unroll
            for (int w = 0; w < CTHREADS / 32; w++) t += ws[w];
            out[0] = t * (1.0f / (float)(NB * VPTS));
            g_cnt_final = 0;   // reset for next launch / graph replay
        }
    }
}

extern "C" void kernel_launch(void* const* d_in, const int* in_sizes, int n_in,
                              void* d_out, int out_size) {
    const float* x = (const float*)d_in[0];
    const float* y = (const float*)d_in[1];
    float* out = (float*)d_out;

    bin_kernel<<<NSETS, 256>>>(x, y);
    chamfer_pruned<<<CBLOCKS, CTHREADS>>>(out);
}

// round 15
// speedup vs baseline: 4.0057x; 4.0057x over previous
#include <cuda_runtime.h>
#include <math_constants.h>

// Chamfer loss: N=8, V=4096, C=3 — bucket-pruned exact NN, smem-staged.
// Each block stages the FULL binned target set (4096 x float4 = 64KB) in
// shared memory; the pruned ring expansion runs at LDS latency. Queries
// are processed in binned order, so a block's 128 queries share one
// (set,batch) and have coherent bucket windows (LDS broadcast).
// Exactness: d^2 >= dx^2; edge buckets unbounded. Determinism: min is
// order-independent; final sum runs over ORIGINAL point indices.
// R14 bug fixed: sBS[NBKT] (the 129th entry) was never initialized with
// 128 threads -> OOB smem scan -> illegal address. Now strided fill.

#define NB 8
#define VPTS 4096
#define NBKT 128
#define XMIN (-4.0f)
#define BW (0.0625f)
#define INVBW (16.0f)
#define NSETS 16              // 2 sets x 8 batches
#define NQTOT (2 * NB * VPTS) // 65536
#define CTHREADS 128
#define CBLOCKS (NQTOT / CTHREADS)   // 512 (32 blocks per (set,batch))

__device__ float4   g_pts[NSETS * VPTS];        // binned points; .w = orig idx bits
__device__ int      g_bstart[NSETS * (NBKT + 1)];
__device__ float    g_dist[NQTOT];              // per-query NN distance, orig order
__device__ unsigned g_cnt_final;                // zero-init; reset after use

__device__ __forceinline__ int bucket_of(float v) {
    int b = (int)floorf((v - XMIN) * INVBW);
    return min(NBKT - 1, max(0, b));
}

// ---------------- binning: one block per (set,batch) ----------------
__global__ __launch_bounds__(256)
void bin_kernel(const float* __restrict__ x, const float* __restrict__ y) {
    const int bi = blockIdx.x;            // 0..15: set = bi>>3, batch = bi&7
    const int s  = bi >> 3;
    const int n  = bi & 7;
    const float* __restrict__ P = (s ? y : x) + (size_t)n * VPTS * 3;
    const int tid = threadIdx.x;

    __shared__ int hist[NBKT];
    __shared__ int offs[NBKT];

    if (tid < NBKT) hist[tid] = 0;
    __syncthreads();

    for (int i = tid; i < VPTS; i += 256)
        atomicAdd(&hist[bucket_of(P[3 * i])], 1);
    __syncthreads();

    if (tid == 0) {
        int run = 0;
        for (int k = 0; k < NBKT; k++) {
            g_bstart[bi * (NBKT + 1) + k] = run;
            offs[k] = run;
            run += hist[k];
        }
        g_bstart[bi * (NBKT + 1) + NBKT] = VPTS;
    }
    __syncthreads();

    for (int i = tid; i < VPTS; i += 256) {
        float a = P[3 * i], b = P[3 * i + 1], c = P[3 * i + 2];
        int k = bucket_of(a);
        int pos = atomicAdd(&offs[k], 1);
        g_pts[bi * VPTS + pos] = make_float4(a, b, c, __int_as_float(i));
    }
}

// ---------------- pruned NN from smem + fused final reduction --------
extern __shared__ float4 sT[];   // 4096 x 16B = 64KB binned target set

__device__ __forceinline__ void scan_bucket_s(int t0, int t1, float4 q,
                                              float& best) {
    #pragma unroll 4
    for (int t = t0; t < t1; t++) {
        float4 p = sT[t];
        float dx = q.x - p.x;
        float dy = q.y - p.y;
        float dz = q.z - p.z;
        float d2 = fmaf(dx, dx, fmaf(dy, dy, dz * dz));
        best = fminf(best, d2);
    }
}

__global__ __launch_bounds__(CTHREADS)
void chamfer_pruned(float* __restrict__ out) {
    const int tid = threadIdx.x;
    const int qid = blockIdx.x * CTHREADS + tid;   // 0..65535
    const int s   = qid / (NB * VPTS);             // query set
    const int rem = qid - s * (NB * VPTS);
    const int n   = rem / VPTS;
    const int i   = rem - n * VPTS;                // position in binned order

    const int tb = (1 - s) * NB + n;               // target (set,batch)

    // Stage the full binned target set in smem (coalesced fill).
    const float4* __restrict__ TP = g_pts + tb * VPTS;
    #pragma unroll
    for (int p = tid; p < VPTS; p += CTHREADS)
        sT[p] = TP[p];

    // Bucket starts (NBKT+1 = 129 entries -> strided fill covers all).
    __shared__ int sBS[NBKT + 1];
    const int* __restrict__ bs = g_bstart + tb * (NBKT + 1);
    for (int p = tid; p <= NBKT; p += CTHREADS)
        sBS[p] = bs[p];
    __syncthreads();

    const float4 q = g_pts[(s * NB + n) * VPTS + i];
    const int k0 = bucket_of(q.x);
    float best = CUDART_INF_F;

    // own bucket first
    scan_bucket_s(sBS[k0], sBS[k0 + 1], q, best);

    // expand rings; prune exactly on x-gap^2 >= best d^2
    int dl = k0 - 1, dr = k0 + 1;
    for (;;) {
        bool doneL, doneR;
        float gl = 0.f, gr = 0.f;
        if (dl < 0) doneL = true;
        else { gl = q.x - (XMIN + (float)(dl + 1) * BW); doneL = (gl * gl >= best); }
        if (dr > NBKT - 1) doneR = true;
        else { gr = (XMIN + (float)dr * BW) - q.x; doneR = (gr * gr >= best); }
        if (doneL && doneR) break;
        if (!doneL) { scan_bucket_s(sBS[dl], sBS[dl + 1], q, best); dl--; }
        if (!doneR) { scan_bucket_s(sBS[dr], sBS[dr + 1], q, best); dr++; }
    }

    // write to ORIGINAL index order (deterministic final sum)
    const int orig = __float_as_int(q.w);
    g_dist[(s * NB + n) * VPTS + orig] = sqrtf(fmaxf(best, 0.0f));
    __threadfence();
    __syncthreads();

    // elect last block for the final deterministic reduction
    __shared__ bool isLast;
    if (tid == 0)
        isLast = (atomicAdd(&g_cnt_final, 1u) == CBLOCKS - 1);
    __syncthreads();

    if (isLast) {
        __threadfence();   // acquire all g_dist writes
        // 65536 floats, 128 threads: 512 consecutive each, fixed order.
        const float4* dv = reinterpret_cast<const float4*>(g_dist) + tid * 128;
        float a0 = 0.f, a1 = 0.f, a2 = 0.f, a3 = 0.f;
        #pragma unroll 4
        for (int j = 0; j < 128; j++) {
            float4 v = dv[j];
            a0 += v.x; a1 += v.y; a2 += v.z; a3 += v.w;
        }
        float v = (a0 + a1) + (a2 + a3);
        #pragma unroll
        for (int off = 16; off > 0; off >>= 1)
            v += __shfl_down_sync(0xffffffffu, v, off);
        __shared__ float ws[CTHREADS / 32];
        if ((tid & 31) == 0) ws[tid >> 5] = v;
        __syncthreads();
        if (tid == 0) {
            float t = 0.f;
            #pragma unroll
            for (int w = 0; w < CTHREADS / 32; w++) t += ws[w];
            out[0] = t * (1.0f / (float)(NB * VPTS));
            g_cnt_final = 0;   // reset for next launch / graph replay
        }
    }
}

extern "C" void kernel_launch(void* const* d_in, const int* in_sizes, int n_in,
                              void* d_out, int out_size) {
    const float* x = (const float*)d_in[0];
    const float* y = (const float*)d_in[1];
    float* out = (float*)d_out;

    bin_kernel<<<NSETS, 256>>>(x, y);

    cudaFuncSetAttribute(chamfer_pruned,
                         cudaFuncAttributeMaxDynamicSharedMemorySize,
                         VPTS * (int)sizeof(float4));
    chamfer_pruned<<<CBLOCKS, CTHREADS, VPTS * sizeof(float4)>>>(out);
}